// round 14
// baseline (speedup 1.0000x reference)
#include <cuda_runtime.h>

#define NQ      12
#define NT      512         // threads per CTA (16 warps)
#define NR      8           // amplitudes per thread
#define NLAYERS 4
#define XP      9           // padded row pitch (u64), rows of 8
#define XSZ     (512 * XP)  // u64 elements per exchange buffer (512 rows)
#define PHYS(n) ((n) + ((n) >> 3))   // (n>>3)*XP + (n&7)

typedef unsigned long long u64;

// ---- packed f32x2 helpers (re in lo 32 bits, im in hi 32 bits) ----
__device__ __forceinline__ u64 pack2(float lo, float hi) {
    u64 r; asm("mov.b64 %0, {%1, %2};" : "=l"(r) : "f"(lo), "f"(hi)); return r;
}
__device__ __forceinline__ void unpack2(u64 v, float& lo, float& hi) {
    asm("mov.b64 {%0, %1}, %2;" : "=f"(lo), "=f"(hi) : "l"(v));
}
__device__ __forceinline__ u64 swap2(u64 v) {
    u64 r;
    asm("{\n\t.reg .b32 l, h;\n\tmov.b64 {l, h}, %1;\n\tmov.b64 %0, {h, l};\n\t}"
        : "=l"(r) : "l"(v));
    return r;
}
__device__ __forceinline__ u64 ffma2(u64 a, u64 b, u64 c) {
    u64 r; asm("fma.rn.f32x2 %0, %1, %2, %3;" : "=l"(r) : "l"(a), "l"(b), "l"(c)); return r;
}
__device__ __forceinline__ u64 fmul2(u64 a, u64 b) {
    u64 r; asm("mul.rn.f32x2 %0, %1, %2;" : "=l"(r) : "l"(a), "l"(b)); return r;
}
__device__ __forceinline__ float2 cmul(float2 a, float2 b) {
    return make_float2(fmaf(-a.y, b.y, a.x * b.x), fmaf(a.y, b.x, a.x * b.y));
}

// ---- REAL RY gate on register bit P (P in 0..2): coeffs [C,S,NS,pad] ----
template<int P>
__device__ __forceinline__ void gate_ry(u64* st, const u64* g) {
    ulonglong2 cs = *(const ulonglong2*)(g);   // C, S
    u64 NS = g[2];
#pragma unroll
    for (int k = 0; k < NR / 2; k++) {
        const int r0 = ((k >> P) << (P + 1)) | (k & ((1 << P) - 1));
        const int r1 = r0 | (1 << P);
        u64 m0 = st[r0], m1 = st[r1];
        st[r0] = ffma2(NS,   m1, fmul2(cs.x, m0));   // c*m0 - s*m1
        st[r1] = ffma2(cs.x, m1, fmul2(cs.y, m0));   // s*m0 + c*m1
    }
}

// ======================= layouts =======================
// amp index n[11:0], wire q <-> bit (11-q). phys(n) = n + (n>>3). t bits t8..t0.
// Layout A: n = (t<<3)|r                      reg = n[2:0]  (wires 9,10,11)
// Layout B: n = ((t>>3)<<6)|(r<<3)|(t&7)      reg = n[5:3]  (wires 6,7,8)
// Layout C: n = ((t>>6)<<9)|(r<<6)|(t&63)     reg = n[8:6]  (wires 3,4,5)
// Layout D: n = (r<<9)|t                      reg = n[11:9] (wires 0,1,2)
// A<->B warp-local (rows (t&~7)|r within warp). B<->C and C<->D cross-warp (CTA).
// CTA round-trips strictly alternate buffers x0/x1 -> one __syncthreads each.

#define ADDR_A(t, r) ((t) * XP + (r))
#define ADDR_B(t, r) (((((t) >> 3) << 3) | (r)) * XP + ((t) & 7))
#define ADDR_C(t, r) (((((t) >> 6) << 6) | ((r) << 3) | (((t) >> 3) & 7)) * XP + ((t) & 7))
#define ADDR_D(t, r) (((((r) << 6) | ((t) >> 3))) * XP + ((t) & 7))

__device__ __forceinline__ void exch_A_to_B(u64* st, int t, u64* x) {   // warp-local
#pragma unroll
    for (int r = 0; r < NR; r++) x[ADDR_A(t, r)] = st[r];
    __syncwarp();
#pragma unroll
    for (int r = 0; r < NR; r++) st[r] = x[ADDR_B(t, r)];
    __syncwarp();
}
__device__ __forceinline__ void exch_B_to_A(u64* st, int t, u64* x) {   // warp-local
#pragma unroll
    for (int r = 0; r < NR; r++) x[ADDR_B(t, r)] = st[r];
    __syncwarp();
#pragma unroll
    for (int r = 0; r < NR; r++) st[r] = x[ADDR_A(t, r)];
    __syncwarp();
}
__device__ __forceinline__ void exch_B_to_C(u64* st, int t, u64* x) {   // CTA, 1 bar
#pragma unroll
    for (int r = 0; r < NR; r++) x[ADDR_B(t, r)] = st[r];
    __syncthreads();
#pragma unroll
    for (int r = 0; r < NR; r++) st[r] = x[ADDR_C(t, r)];
}
__device__ __forceinline__ void exch_C_to_B(u64* st, int t, u64* x) {   // CTA, 1 bar
#pragma unroll
    for (int r = 0; r < NR; r++) x[ADDR_C(t, r)] = st[r];
    __syncthreads();
#pragma unroll
    for (int r = 0; r < NR; r++) st[r] = x[ADDR_B(t, r)];
    __syncwarp();   // reads own rows; order before this warp's next WL write
}
__device__ __forceinline__ void exch_C_to_D(u64* st, int t, u64* x) {   // CTA, 1 bar
#pragma unroll
    for (int r = 0; r < NR; r++) x[ADDR_C(t, r)] = st[r];
    __syncthreads();
#pragma unroll
    for (int r = 0; r < NR; r++) st[r] = x[ADDR_D(t, r)];
}
__device__ __forceinline__ void exch_D_to_C(u64* st, int t, u64* x) {   // CTA, 1 bar
#pragma unroll
    for (int r = 0; r < NR; r++) x[ADDR_D(t, r)] = st[r];
    __syncthreads();
#pragma unroll
    for (int r = 0; r < NR; r++) st[r] = x[ADDR_C(t, r)];
}

// ======================= RY-only sweeps =======================
// gate coeffs for wire q at G + q*4. Smallest wire of each triple -> reg bit 2.
// Buffer schedule (strict x0/x1 alternation incl. cnot): see layer code.
__device__ __forceinline__ void sweep_D_to_A(u64* st, const u64* G, int t, u64* x0, u64* x1) {
    gate_ry<2>(st, G + 0 * 4);  gate_ry<1>(st, G + 1 * 4);  gate_ry<0>(st, G + 2 * 4);
    exch_D_to_C(st, t, x0);
    gate_ry<2>(st, G + 3 * 4);  gate_ry<1>(st, G + 4 * 4);  gate_ry<0>(st, G + 5 * 4);
    exch_C_to_B(st, t, x1);
    gate_ry<2>(st, G + 6 * 4);  gate_ry<1>(st, G + 7 * 4);  gate_ry<0>(st, G + 8 * 4);
    exch_B_to_A(st, t, x1);     // WL on x1: prior x1 reads were own-row-only
    gate_ry<2>(st, G + 9 * 4);  gate_ry<1>(st, G + 10 * 4); gate_ry<0>(st, G + 11 * 4);
}
__device__ __forceinline__ void sweep_A_to_D(u64* st, const u64* G, int t, u64* x0, u64* x1) {
    gate_ry<2>(st, G + 9 * 4);  gate_ry<1>(st, G + 10 * 4); gate_ry<0>(st, G + 11 * 4);
    exch_A_to_B(st, t, x1);     // WL on x1 (last CTA use of x1 >= 2 bars ago)
    gate_ry<2>(st, G + 6 * 4);  gate_ry<1>(st, G + 7 * 4);  gate_ry<0>(st, G + 8 * 4);
    exch_B_to_C(st, t, x1);
    gate_ry<2>(st, G + 3 * 4);  gate_ry<1>(st, G + 4 * 4);  gate_ry<0>(st, G + 5 * 4);
    exch_C_to_D(st, t, x0);
    gate_ry<2>(st, G + 0 * 4);  gate_ry<1>(st, G + 1 * 4);  gate_ry<0>(st, G + 2 * 4);
}

// ======================= global diagonal application =======================
// Layout A: wires 0..8 = t8..t0, wires 9..11 = r2..r0.
__device__ __forceinline__ void diag_A(u64* st, int t, const float2 (*P)[2]) {
    float2 p01 = cmul(P[0][(t >> 8) & 1], P[1][(t >> 7) & 1]);
    float2 p23 = cmul(P[2][(t >> 6) & 1], P[3][(t >> 5) & 1]);
    float2 p45 = cmul(P[4][(t >> 4) & 1], P[5][(t >> 3) & 1]);
    float2 p67 = cmul(P[6][(t >> 2) & 1], P[7][(t >> 1) & 1]);
    float2 ph  = cmul(cmul(cmul(p01, p23), cmul(p45, p67)), P[8][t & 1]);
    u64 Ac[8], Bc[8];
    float2 p9A = cmul(ph, P[9][0]), p9B = cmul(ph, P[9][1]);
#pragma unroll
    for (int i = 0; i < 8; i++) {
        float2 e = cmul((i & 4) ? p9B : p9A,
                        cmul(P[10][(i >> 1) & 1], P[11][i & 1]));
        Ac[i] = pack2(e.x, e.x);  Bc[i] = pack2(-e.y, e.y);
    }
#pragma unroll
    for (int r = 0; r < NR; r++)
        st[r] = ffma2(Bc[r], swap2(st[r]), fmul2(Ac[r], st[r]));
}
// Layout D: wires 3..11 = t8..t0, wires 0..2 = r2..r0.
__device__ __forceinline__ void diag_D(u64* st, int t, const float2 (*P)[2]) {
    float2 p01 = cmul(P[3][(t >> 8) & 1], P[4][(t >> 7) & 1]);
    float2 p23 = cmul(P[5][(t >> 6) & 1], P[6][(t >> 5) & 1]);
    float2 p45 = cmul(P[7][(t >> 4) & 1], P[8][(t >> 3) & 1]);
    float2 p67 = cmul(P[9][(t >> 2) & 1], P[10][(t >> 1) & 1]);
    float2 ph  = cmul(cmul(cmul(p01, p23), cmul(p45, p67)), P[11][t & 1]);
    u64 Ac[8], Bc[8];
    float2 p0A = cmul(ph, P[0][0]), p0B = cmul(ph, P[0][1]);
#pragma unroll
    for (int i = 0; i < 8; i++) {
        float2 e = cmul((i & 4) ? p0B : p0A,
                        cmul(P[1][(i >> 1) & 1], P[2][i & 1]));
        Ac[i] = pack2(e.x, e.x);  Bc[i] = pack2(-e.y, e.y);
    }
#pragma unroll
    for (int r = 0; r < NR; r++)
        st[r] = ffma2(Bc[r], swap2(st[r]), fmul2(Ac[r], st[r]));
}

// ======================= batched CNOT ring (smem unit-image basis) =======================
// U[i] = image of n-bit-i unit vector under M = T0∘...∘T11 (reverse ring order).
template<bool LAYOUT_A>
__device__ __forceinline__ void cnotx(u64* st, int t, u64* x, const unsigned* U) {
    // thread-bit images: LAYOUT_A -> n bits 3..11; LAYOUT_D -> n bits 0..8
    const unsigned* UT = U + (LAYOUT_A ? 3 : 0);
    unsigned v0 = 0;
#pragma unroll
    for (int j = 0; j < 9; j++)
        if (t & (1 << j)) v0 ^= UT[j];
#pragma unroll
    for (int r = 0; r < NR; r++) {
        unsigned n = LAYOUT_A ? (((unsigned)t << 3) | (unsigned)r)
                              : (((unsigned)r << 9) | (unsigned)t);
        x[PHYS(n)] = st[r];
    }
    __syncthreads();
    // reg-bit images: LAYOUT_A -> n bits 0..2; LAYOUT_D -> n bits 9..11
    const unsigned* UR = U + (LAYOUT_A ? 0 : 9);
    unsigned u0 = UR[0], u1 = UR[1], u2 = UR[2];
#pragma unroll
    for (int r = 0; r < NR; r++) {            // r compile-time -> constant-folded XORs
        unsigned m = v0;
        if (r & 4) m ^= u2;
        if (r & 2) m ^= u1;
        if (r & 1) m ^= u0;
        st[r] = x[PHYS(m)];
    }
}

// GF(2) ring transform (reverse order), setup threads only.
__device__ __forceinline__ unsigned ring_map(unsigned v, unsigned mask) {
#pragma unroll
    for (int k = NQ - 1; k >= 0; k--) {
        if (mask & (1u << k)) {
            const int cb = 11 - k;
            const int tb = 11 - ((k + 1) % NQ);
            v ^= ((v >> cb) & 1u) << tb;
        }
    }
    return v;
}

__device__ __forceinline__ float wred(float v) {
#pragma unroll
    for (int o = 16; o; o >>= 1) v += __shfl_xor_sync(0xFFFFFFFFu, v, o);
    return v;
}

__global__ void __launch_bounds__(NT)
qsim_kernel(const float* __restrict__ x,       // (B, 12)
            const float* __restrict__ w,       // (4, 12, 3)
            const float* __restrict__ ent,     // (4, 12)
            float* __restrict__ out)           // (B, 12)
{
    extern __shared__ __align__(16) u64 dsm[];       // 2 exchange buffers (dynamic)
    u64* x0 = dsm;
    u64* x1 = dsm + XSZ;

    __shared__ __align__(16) u64 Usm[48 * 4];        // RY coeffs: C,S,NS,pad per gate
    __shared__ float2 Phs1[48][2];                   // RZ(phi) phases per gate per bit
    __shared__ float2 Phs2[48][2];                   // RZ(omega) phases per gate per bit
    __shared__ float red[(NT / 32) * NQ];
    __shared__ float2 encV[NQ][2];                   // encoding amps w/ layer-0 D1 folded
    __shared__ unsigned maskbits[NLAYERS];
    __shared__ __align__(16) unsigned units_sm[NLAYERS][16];  // bit images (12 used)

    const int b    = blockIdx.x;
    const int t    = threadIdx.x;
    const int lane = t & 31;
    const int wid  = t >> 5;

    // ---- precompute gates/phases/masks (parallel across threads) ----
    if (t < 64) {
        const float PI = 3.14159265358979323846f;
        if (t < NQ) {
            // encoding on wire t: column 0 of RZ(x^2 pi) RY(x pi), times layer-0 RZ(phi)
            float xv = __ldg(&x[b * NQ + t]);
            float s, c;  sincosf(0.5f * PI * xv, &s, &c);
            float sh, ch; sincosf(0.5f * PI * xv * xv, &sh, &ch);
            float2 a0 = make_float2( c * ch, -c * sh);
            float2 a1 = make_float2( s * ch,  s * sh);
            float pf = __ldg(&w[t * 3 + 0]);        // layer 0, wire t: phi
            float sp, cp; sincosf(0.5f * pf, &sp, &cp);
            encV[t][0] = cmul(a0, make_float2(cp, -sp));
            encV[t][1] = cmul(a1, make_float2(cp,  sp));
        } else if (t < 60) {
            int gi = t - NQ;   // = l*12 + q
            float phi = __ldg(&w[gi * 3 + 0]);
            float th  = __ldg(&w[gi * 3 + 1]);
            float om  = __ldg(&w[gi * 3 + 2]);
            float s, c;  sincosf(0.5f * th, &s, &c);
            u64* g = &Usm[gi * 4];
            g[0] = pack2(c, c);  g[1] = pack2(s, s);  g[2] = pack2(-s, -s);
            float sp, cp; sincosf(0.5f * phi, &sp, &cp);
            Phs1[gi][0] = make_float2(cp, -sp);
            Phs1[gi][1] = make_float2(cp,  sp);
            float so, co; sincosf(0.5f * om, &so, &co);
            Phs2[gi][0] = make_float2(co, -so);
            Phs2[gi][1] = make_float2(co,  so);
        } else {
            int l = t - 60;    // t in [60,64): build maskbits[l]
            unsigned mm = 0;
#pragma unroll
            for (int i = 0; i < NQ; i++)
                mm |= (__ldg(&ent[l * NQ + i]) > 0.5f ? 1u : 0u) << i;
            maskbits[l] = mm;
        }
    }
    __syncthreads();

    // ---- ring-perm unit images (threads 64..111); consumed after >=1 CTA bar ----
    if (t >= 64 && t < 64 + NLAYERS * NQ) {
        int idx = t - 64, l = idx / NQ, i = idx % NQ;
        units_sm[l][i] = ring_map(1u << i, maskbits[l]);
    }

    // ---- encoded state (incl. layer-0 RZ(phi)) is a PRODUCT state; build in layout D ----
    // n = (r<<9)|t: wires 0..2 = r2..r0, wires 3..11 = t8..t0.
    u64 st[NR];
    {
        float2 q34 = cmul(encV[3][(t >> 8) & 1], encV[4][(t >> 7) & 1]);
        float2 q56 = cmul(encV[5][(t >> 6) & 1], encV[6][(t >> 5) & 1]);
        float2 q78 = cmul(encV[7][(t >> 4) & 1], encV[8][(t >> 3) & 1]);
        float2 q9A = cmul(encV[9][(t >> 2) & 1], encV[10][(t >> 1) & 1]);
        float2 cm  = cmul(cmul(cmul(q34, q56), cmul(q78, q9A)), encV[11][t & 1]);
        float2 e0A = cmul(cm, encV[0][0]), e0B = cmul(cm, encV[0][1]);
#pragma unroll
        for (int r = 0; r < NR; r++) {
            float2 a = cmul((r & 4) ? e0B : e0A,
                            cmul(encV[1][(r >> 1) & 1], encV[2][r & 1]));
            st[r] = pack2(a.x, a.y);
        }
    }

    // ---- layers: RY sweep, D2 diag, CNOT perm, D1 diag of next layer ----
    // CTA RT buffer order: L0 [x0,x1,cnot x0] L1 [x1,x0,cnot x1] L2,L3 repeat.
    {
        sweep_D_to_A(st, Usm +  0 * 48, t, x0, x1);     // layer 0 RYs (D->C:x0, C->B:x1)
        diag_A(st, t, &Phs2[0]);                        // D2_0
        cnotx<true>(st, t, x0, units_sm[0]);
        diag_A(st, t, &Phs1[12]);                       // D1_1

        sweep_A_to_D(st, Usm +  1 * 48, t, x0, x1);     // layer 1 RYs (B->C:x1, C->D:x0)
        diag_D(st, t, &Phs2[12]);                       // D2_1
        cnotx<false>(st, t, x1, units_sm[1]);
        diag_D(st, t, &Phs1[24]);                       // D1_2

        sweep_D_to_A(st, Usm +  2 * 48, t, x0, x1);     // layer 2 RYs
        diag_A(st, t, &Phs2[24]);                       // D2_2
        cnotx<true>(st, t, x0, units_sm[2]);
        diag_A(st, t, &Phs1[36]);                       // D1_3

        sweep_A_to_D(st, Usm +  3 * 48, t, x0, x1);     // layer 3 RYs
        // D2_3 dropped: |amp|^2 is phase-invariant
        cnotx<false>(st, t, x1, units_sm[3]);
    }

    // ---- readout in layout D: wires 0..2 = r2..r0, 3..6 = wid bits, 7..11 = lane bits ----
    float psum = 0.f, a0 = 0.f, a1 = 0.f, a2 = 0.f;
#pragma unroll
    for (int r = 0; r < NR; r++) {
        float re, im; unpack2(st[r], re, im);
        float p = fmaf(re, re, im * im);
        psum += p;
        a0 += (r & 4) ? -p : p;   // wire 0 = r2
        a1 += (r & 2) ? -p : p;   // wire 1 = r1
        a2 += (r & 1) ? -p : p;   // wire 2 = r0
    }
    float ra0 = wred(a0), ra1 = wred(a1), ra2 = wred(a2);
    float ps  = wred(psum);
    float s7  = wred((lane & 16) ? -psum : psum);   // wire 7  = t4
    float s8  = wred((lane &  8) ? -psum : psum);   // wire 8  = t3
    float s9  = wred((lane &  4) ? -psum : psum);   // wire 9  = t2
    float s10 = wred((lane &  2) ? -psum : psum);   // wire 10 = t1
    float s11 = wred((lane &  1) ? -psum : psum);   // wire 11 = t0
    if (lane == 0) {
        float* rw = &red[wid * NQ];
        rw[0] = ra0;  rw[1] = ra1;  rw[2] = ra2;
        rw[3] = (wid & 8) ? -ps : ps;    // wire 3 = t8
        rw[4] = (wid & 4) ? -ps : ps;    // wire 4 = t7
        rw[5] = (wid & 2) ? -ps : ps;    // wire 5 = t6
        rw[6] = (wid & 1) ? -ps : ps;    // wire 6 = t5
        rw[7] = s7;  rw[8] = s8;  rw[9] = s9;  rw[10] = s10;  rw[11] = s11;
    }
    __syncthreads();

    if (t < NQ) {
        float s = 0.f;
#pragma unroll
        for (int wi = 0; wi < NT / 32; wi++) s += red[wi * NQ + t];
        out[b * NQ + t] = s;   // SCALE = 1
    }
}

extern "C" void kernel_launch(void* const* d_in, const int* in_sizes, int n_in,
                              void* d_out, int out_size)
{
    const float* x   = (const float*)d_in[0];   // (B, 12)
    const float* w   = (const float*)d_in[1];   // (4, 12, 3)
    const float* ent = (const float*)d_in[2];   // (4, 12)
    float* out = (float*)d_out;                 // (B, 12)

    const size_t shmem = 2 * XSZ * sizeof(u64);  // 73728 B dynamic
    cudaFuncSetAttribute((const void*)qsim_kernel,
                         cudaFuncAttributeMaxDynamicSharedMemorySize, (int)shmem);

    int B = in_sizes[0] / NQ;
    qsim_kernel<<<B, NT, shmem>>>(x, w, ent, out);
}

// round 15
// speedup vs baseline: 1.2931x; 1.2931x over previous
#include <cuda_runtime.h>

#define NQ      12
#define NT      256         // threads per CTA
#define NR      16          // amplitudes per thread PER SAMPLE (2 samples/CTA)
#define NLAYERS 4
#define XP      17          // padded row pitch (u64) -> conflict-free transposes
#define XSZ     (NT * XP)   // u64 elements per exchange buffer
#define PHYS(n) ((n) + ((n) >> 4))   // (n>>4)*XP + (n&15)

typedef unsigned long long u64;

// ---- packed f32x2 helpers (re in lo 32 bits, im in hi 32 bits) ----
__device__ __forceinline__ u64 pack2(float lo, float hi) {
    u64 r; asm("mov.b64 %0, {%1, %2};" : "=l"(r) : "f"(lo), "f"(hi)); return r;
}
__device__ __forceinline__ void unpack2(u64 v, float& lo, float& hi) {
    asm("mov.b64 {%0, %1}, %2;" : "=f"(lo), "=f"(hi) : "l"(v));
}
__device__ __forceinline__ u64 swap2(u64 v) {
    u64 r;
    asm("{\n\t.reg .b32 l, h;\n\tmov.b64 {l, h}, %1;\n\tmov.b64 %0, {h, l};\n\t}"
        : "=l"(r) : "l"(v));
    return r;
}
__device__ __forceinline__ u64 ffma2(u64 a, u64 b, u64 c) {
    u64 r; asm("fma.rn.f32x2 %0, %1, %2, %3;" : "=l"(r) : "l"(a), "l"(b), "l"(c)); return r;
}
__device__ __forceinline__ u64 fmul2(u64 a, u64 b) {
    u64 r; asm("mul.rn.f32x2 %0, %1, %2;" : "=l"(r) : "l"(a), "l"(b)); return r;
}
__device__ __forceinline__ float2 cmul(float2 a, float2 b) {
    return make_float2(fmaf(-a.y, b.y, a.x * b.x), fmaf(a.y, b.x, a.x * b.y));
}

// ---- REAL RY gate on register bit P, applied to BOTH samples (shared coeffs) ----
template<int P>
__device__ __forceinline__ void gate_ry2(u64* sa, u64* sb, const u64* g) {
    ulonglong2 cs = *(const ulonglong2*)(g);   // C, S
    u64 NS = g[2];
#pragma unroll
    for (int k = 0; k < NR / 2; k++) {
        const int r0 = ((k >> P) << (P + 1)) | (k & ((1 << P) - 1));
        const int r1 = r0 | (1 << P);
        u64 a0 = sa[r0], a1 = sa[r1];
        u64 b0 = sb[r0], b1 = sb[r1];
        sa[r0] = ffma2(NS,   a1, fmul2(cs.x, a0));
        sb[r0] = ffma2(NS,   b1, fmul2(cs.x, b0));
        sa[r1] = ffma2(cs.x, a1, fmul2(cs.y, a0));
        sb[r1] = ffma2(cs.x, b1, fmul2(cs.y, b0));
    }
}

// ======================= layouts & transposes (R13 schedule, paired) =======================
// amp index n[11:0], wire q <-> bit (11-q). phys(n) = n + (n>>4).
// Layout A: n = (t<<4)|r ; Layout C: n = ((t>>4)<<8)|(r<<4)|(t&15) ; Layout D: n = (r<<8)|t
// Sample a uses buffers xa (sweep) / ya (cnot); sample b uses xb / yb.
// CTA round-trips alternate sweep-buffers and cnot-buffers per sample exactly as R13;
// both samples share each __syncthreads().

#define ADDR_A(t, r) ((t) * XP + (r))
#define ADDR_C(t, r) (((((t) >> 4) << 4) | (r)) * XP + ((t) & 15))
#define ADDR_D(t, r) ((((r) << 4) | ((t) >> 4)) * XP + ((t) & 15))

__device__ __forceinline__ void exch_A_to_C2(u64* sa, u64* sb, int t, u64* xa, u64* xb) { // WL
#pragma unroll
    for (int r = 0; r < NR; r++) { xa[ADDR_A(t, r)] = sa[r]; xb[ADDR_A(t, r)] = sb[r]; }
    __syncwarp();
#pragma unroll
    for (int r = 0; r < NR; r++) { sa[r] = xa[ADDR_C(t, r)]; sb[r] = xb[ADDR_C(t, r)]; }
    __syncwarp();
}
__device__ __forceinline__ void exch_C_to_A2(u64* sa, u64* sb, int t, u64* xa, u64* xb) { // WL
#pragma unroll
    for (int r = 0; r < NR; r++) { xa[ADDR_C(t, r)] = sa[r]; xb[ADDR_C(t, r)] = sb[r]; }
    __syncwarp();
#pragma unroll
    for (int r = 0; r < NR; r++) { sa[r] = xa[ADDR_A(t, r)]; sb[r] = xb[ADDR_A(t, r)]; }
    __syncwarp();
}
__device__ __forceinline__ void exch_C_to_D2(u64* sa, u64* sb, int t, u64* xa, u64* xb) { // CTA
#pragma unroll
    for (int r = 0; r < NR; r++) { xa[ADDR_C(t, r)] = sa[r]; xb[ADDR_C(t, r)] = sb[r]; }
    __syncthreads();
#pragma unroll
    for (int r = 0; r < NR; r++) { sa[r] = xa[ADDR_D(t, r)]; sb[r] = xb[ADDR_D(t, r)]; }
}
__device__ __forceinline__ void exch_D_to_C2(u64* sa, u64* sb, int t, u64* xa, u64* xb) { // CTA
#pragma unroll
    for (int r = 0; r < NR; r++) { xa[ADDR_D(t, r)] = sa[r]; xb[ADDR_D(t, r)] = sb[r]; }
    __syncthreads();
#pragma unroll
    for (int r = 0; r < NR; r++) { sa[r] = xa[ADDR_C(t, r)]; sb[r] = xb[ADDR_C(t, r)]; }
    __syncwarp();   // reads are own-slice; order before this warp's next WL write
}

// ======================= RY-only sweeps (paired) =======================
__device__ __forceinline__ void sweep_A_to_D2(u64* sa, u64* sb, const u64* G, int t,
                                              u64* xa, u64* xb) {
    gate_ry2<3>(sa, sb, G +  8 * 4);  gate_ry2<2>(sa, sb, G +  9 * 4);
    gate_ry2<1>(sa, sb, G + 10 * 4);  gate_ry2<0>(sa, sb, G + 11 * 4);
    exch_A_to_C2(sa, sb, t, xa, xb);
    gate_ry2<3>(sa, sb, G +  4 * 4);  gate_ry2<2>(sa, sb, G +  5 * 4);
    gate_ry2<1>(sa, sb, G +  6 * 4);  gate_ry2<0>(sa, sb, G +  7 * 4);
    exch_C_to_D2(sa, sb, t, xa, xb);
    gate_ry2<3>(sa, sb, G +  0 * 4);  gate_ry2<2>(sa, sb, G +  1 * 4);
    gate_ry2<1>(sa, sb, G +  2 * 4);  gate_ry2<0>(sa, sb, G +  3 * 4);
}
__device__ __forceinline__ void sweep_D_to_A2(u64* sa, u64* sb, const u64* G, int t,
                                              u64* xa, u64* xb) {
    gate_ry2<3>(sa, sb, G +  0 * 4);  gate_ry2<2>(sa, sb, G +  1 * 4);
    gate_ry2<1>(sa, sb, G +  2 * 4);  gate_ry2<0>(sa, sb, G +  3 * 4);
    exch_D_to_C2(sa, sb, t, xa, xb);
    gate_ry2<3>(sa, sb, G +  4 * 4);  gate_ry2<2>(sa, sb, G +  5 * 4);
    gate_ry2<1>(sa, sb, G +  6 * 4);  gate_ry2<0>(sa, sb, G +  7 * 4);
    exch_C_to_A2(sa, sb, t, xa, xb);
    gate_ry2<3>(sa, sb, G +  8 * 4);  gate_ry2<2>(sa, sb, G +  9 * 4);
    gate_ry2<1>(sa, sb, G + 10 * 4);  gate_ry2<0>(sa, sb, G + 11 * 4);
}

// ======================= global diagonals (tables built ONCE, applied to both) =======================
__device__ __forceinline__ void diag_A2(u64* sa, u64* sb, int t, const float2 (*P)[2]) {
    float2 p01 = cmul(P[0][(t >> 7) & 1], P[1][(t >> 6) & 1]);
    float2 p23 = cmul(P[2][(t >> 5) & 1], P[3][(t >> 4) & 1]);
    float2 p45 = cmul(P[4][(t >> 3) & 1], P[5][(t >> 2) & 1]);
    float2 p67 = cmul(P[6][(t >> 1) & 1], P[7][t & 1]);
    float2 ph  = cmul(cmul(p01, p23), cmul(p45, p67));
    u64 Ah[4], Bh[4], Al[4], Bl[4];
#pragma unroll
    for (int i = 0; i < 4; i++) {
        float2 hi = cmul(ph, cmul(P[8][(i >> 1) & 1], P[9][i & 1]));
        float2 lo = cmul(P[10][(i >> 1) & 1], P[11][i & 1]);
        Ah[i] = pack2(hi.x, hi.x);  Bh[i] = pack2(-hi.y, hi.y);
        Al[i] = pack2(lo.x, lo.x);  Bl[i] = pack2(-lo.y, lo.y);
    }
#pragma unroll
    for (int r = 0; r < NR; r++) {
        u64 a = sa[r], b = sb[r];
        a = ffma2(Bh[r >> 2], swap2(a), fmul2(Ah[r >> 2], a));
        b = ffma2(Bh[r >> 2], swap2(b), fmul2(Ah[r >> 2], b));
        a = ffma2(Bl[r & 3],  swap2(a), fmul2(Al[r & 3],  a));
        b = ffma2(Bl[r & 3],  swap2(b), fmul2(Al[r & 3],  b));
        sa[r] = a; sb[r] = b;
    }
}
__device__ __forceinline__ void diag_D2(u64* sa, u64* sb, int t, const float2 (*P)[2]) {
    float2 p01 = cmul(P[4][(t >> 7) & 1], P[5][(t >> 6) & 1]);
    float2 p23 = cmul(P[6][(t >> 5) & 1], P[7][(t >> 4) & 1]);
    float2 p45 = cmul(P[8][(t >> 3) & 1], P[9][(t >> 2) & 1]);
    float2 p67 = cmul(P[10][(t >> 1) & 1], P[11][t & 1]);
    float2 ph  = cmul(cmul(p01, p23), cmul(p45, p67));
    u64 Ah[4], Bh[4], Al[4], Bl[4];
#pragma unroll
    for (int i = 0; i < 4; i++) {
        float2 hi = cmul(ph, cmul(P[0][(i >> 1) & 1], P[1][i & 1]));
        float2 lo = cmul(P[2][(i >> 1) & 1], P[3][i & 1]);
        Ah[i] = pack2(hi.x, hi.x);  Bh[i] = pack2(-hi.y, hi.y);
        Al[i] = pack2(lo.x, lo.x);  Bl[i] = pack2(-lo.y, lo.y);
    }
#pragma unroll
    for (int r = 0; r < NR; r++) {
        u64 a = sa[r], b = sb[r];
        a = ffma2(Bh[r >> 2], swap2(a), fmul2(Ah[r >> 2], a));
        b = ffma2(Bh[r >> 2], swap2(b), fmul2(Ah[r >> 2], b));
        a = ffma2(Bl[r & 3],  swap2(a), fmul2(Al[r & 3],  a));
        b = ffma2(Bl[r & 3],  swap2(b), fmul2(Al[r & 3],  b));
        sa[r] = a; sb[r] = b;
    }
}

// ======================= batched CNOT ring (shared indices, paired data) =======================
template<bool LAYOUT_A>
__device__ __forceinline__ void cnotx2(u64* sa, u64* sb, int t, u64* xa, u64* xb,
                                       const unsigned* U) {
    uint4 ua = *(const uint4*)(U + (LAYOUT_A ? 4 : 0));
    uint4 ub = *(const uint4*)(U + (LAYOUT_A ? 8 : 4));
    unsigned v0 = 0;
    if (t & 1)   v0 ^= ua.x;
    if (t & 2)   v0 ^= ua.y;
    if (t & 4)   v0 ^= ua.z;
    if (t & 8)   v0 ^= ua.w;
    if (t & 16)  v0 ^= ub.x;
    if (t & 32)  v0 ^= ub.y;
    if (t & 64)  v0 ^= ub.z;
    if (t & 128) v0 ^= ub.w;
#pragma unroll
    for (int r = 0; r < NR; r++) {
        unsigned n = LAYOUT_A ? (((unsigned)t << 4) | (unsigned)r)
                              : (((unsigned)r << 8) | (unsigned)t);
        xa[PHYS(n)] = sa[r];  xb[PHYS(n)] = sb[r];
    }
    __syncthreads();
    uint4 ur = *(const uint4*)(U + (LAYOUT_A ? 0 : 8));
#pragma unroll
    for (int r = 0; r < NR; r++) {
        unsigned m = v0;
        if (r & 8) m ^= ur.w;
        if (r & 4) m ^= ur.z;
        if (r & 2) m ^= ur.y;
        if (r & 1) m ^= ur.x;
        sa[r] = xa[PHYS(m)];  sb[r] = xb[PHYS(m)];
    }
}

// GF(2) ring transform (reverse order), setup threads only.
__device__ __forceinline__ unsigned ring_map(unsigned v, unsigned mask) {
#pragma unroll
    for (int k = NQ - 1; k >= 0; k--) {
        if (mask & (1u << k)) {
            const int cb = 11 - k;
            const int tb = 11 - ((k + 1) % NQ);
            v ^= ((v >> cb) & 1u) << tb;
        }
    }
    return v;
}

__device__ __forceinline__ float wred(float v) {
#pragma unroll
    for (int o = 16; o; o >>= 1) v += __shfl_xor_sync(0xFFFFFFFFu, v, o);
    return v;
}

// per-sample readout in layout D (R13's scheme)
__device__ __forceinline__ void readout(const u64* st, int t, int lane, int wid,
                                        float* red, float* outrow) {
    float psum = 0.f, a0 = 0.f, a1 = 0.f, a2 = 0.f, a3 = 0.f;
#pragma unroll
    for (int r = 0; r < NR; r++) {
        float re, im; unpack2(st[r], re, im);
        float p = fmaf(re, re, im * im);
        psum += p;
        a0 += (r & 8) ? -p : p;
        a1 += (r & 4) ? -p : p;
        a2 += (r & 2) ? -p : p;
        a3 += (r & 1) ? -p : p;
    }
    float ra0 = wred(a0), ra1 = wred(a1), ra2 = wred(a2), ra3 = wred(a3);
    float ps  = wred(psum);
    float s7  = wred((lane & 16) ? -psum : psum);
    float s8  = wred((lane &  8) ? -psum : psum);
    float s9  = wred((lane &  4) ? -psum : psum);
    float s10 = wred((lane &  2) ? -psum : psum);
    float s11 = wred((lane &  1) ? -psum : psum);
    if (lane == 0) {
        float* rw = &red[wid * NQ];
        rw[0] = ra0;  rw[1] = ra1;  rw[2] = ra2;  rw[3] = ra3;
        rw[4] = (wid & 4) ? -ps : ps;
        rw[5] = (wid & 2) ? -ps : ps;
        rw[6] = (wid & 1) ? -ps : ps;
        rw[7] = s7;  rw[8] = s8;  rw[9] = s9;  rw[10] = s10;  rw[11] = s11;
    }
    __syncthreads();
    if (t < NQ) {
        float s = 0.f;
#pragma unroll
        for (int wi = 0; wi < NT / 32; wi++) s += red[wi * NQ + t];
        outrow[t] = s;   // SCALE = 1
    }
}

__global__ void __launch_bounds__(NT)
qsim_kernel(const float* __restrict__ x,       // (B, 12)
            const float* __restrict__ w,       // (4, 12, 3)
            const float* __restrict__ ent,     // (4, 12)
            float* __restrict__ out)           // (B, 12)
{
    extern __shared__ __align__(16) u64 dsm[];       // 4 exchange buffers (dynamic)
    u64* xa0 = dsm;                                   // sample a: sweep
    u64* xa1 = dsm + XSZ;                             // sample a: cnot
    u64* xb0 = dsm + 2 * XSZ;                         // sample b: sweep
    u64* xb1 = dsm + 3 * XSZ;                         // sample b: cnot

    __shared__ __align__(16) u64 Usm[48 * 4];         // RY coeffs (shared by both samples)
    __shared__ float2 Phs1[48][2];                    // RZ(phi) phases
    __shared__ float2 Phs2[48][2];                    // RZ(omega) phases
    __shared__ float redA[(NT / 32) * NQ];
    __shared__ float redB[(NT / 32) * NQ];
    __shared__ float2 encV[2][NQ][2];                 // per-sample encoding amps (w/ D1_0)
    __shared__ unsigned maskbits[NLAYERS];
    __shared__ __align__(16) unsigned units_sm[NLAYERS][16];

    const int b0   = blockIdx.x * 2;                  // this CTA's two samples
    const int t    = threadIdx.x;
    const int lane = t & 31;
    const int wid  = t >> 5;

    // ---- precompute (parallel across threads; weights shared, encoding per sample) ----
    if (t < 128) {
        const float PI = 3.14159265358979323846f;
        if (t < 2 * NQ) {
            int s = t / NQ, q = t % NQ;
            float xv = __ldg(&x[(b0 + s) * NQ + q]);
            float sn, c;  sincosf(0.5f * PI * xv, &sn, &c);
            float sh, ch; sincosf(0.5f * PI * xv * xv, &sh, &ch);
            float2 a0 = make_float2( c * ch, -c * sh);
            float2 a1 = make_float2( sn * ch,  sn * sh);
            float pf = __ldg(&w[q * 3 + 0]);          // layer 0 phi
            float sp, cp; sincosf(0.5f * pf, &sp, &cp);
            encV[s][q][0] = cmul(a0, make_float2(cp, -sp));
            encV[s][q][1] = cmul(a1, make_float2(cp,  sp));
        } else if (t < 24 + 48) {
            int gi = t - 24;   // 0..47
            float phi = __ldg(&w[gi * 3 + 0]);
            float th  = __ldg(&w[gi * 3 + 1]);
            float om  = __ldg(&w[gi * 3 + 2]);
            float sn, c;  sincosf(0.5f * th, &sn, &c);
            u64* g = &Usm[gi * 4];
            g[0] = pack2(c, c);  g[1] = pack2(sn, sn);  g[2] = pack2(-sn, -sn);
            float sp, cp; sincosf(0.5f * phi, &sp, &cp);
            Phs1[gi][0] = make_float2(cp, -sp);
            Phs1[gi][1] = make_float2(cp,  sp);
            float so, co; sincosf(0.5f * om, &so, &co);
            Phs2[gi][0] = make_float2(co, -so);
            Phs2[gi][1] = make_float2(co,  so);
        } else if (t < 76) {
            int l = t - 72;
            unsigned mm = 0;
#pragma unroll
            for (int i = 0; i < NQ; i++)
                mm |= (__ldg(&ent[l * NQ + i]) > 0.5f ? 1u : 0u) << i;
            maskbits[l] = mm;
        }
    }
    __syncthreads();

    // ---- ring-perm unit images (threads 128..175); consumed after next CTA barrier ----
    if (t >= 128 && t < 128 + NLAYERS * NQ) {
        int idx = t - 128, l = idx / NQ, i = idx % NQ;
        units_sm[l][i] = ring_map(1u << i, maskbits[l]);
    }

    // ---- product-state init for both samples, layout D ----
    u64 sa[NR], sb[NR];
#pragma unroll
    for (int s = 0; s < 2; s++) {
        const float2 (*eV)[2] = encV[s];
        float2 q45 = cmul(eV[4][(t >> 7) & 1], eV[5][(t >> 6) & 1]);
        float2 q67 = cmul(eV[6][(t >> 5) & 1], eV[7][(t >> 4) & 1]);
        float2 q89 = cmul(eV[8][(t >> 3) & 1], eV[9][(t >> 2) & 1]);
        float2 qAB = cmul(eV[10][(t >> 1) & 1], eV[11][t & 1]);
        float2 cm  = cmul(cmul(q45, q67), cmul(q89, qAB));
        float2 p01[4], p23[4];
#pragma unroll
        for (int i = 0; i < 4; i++) {
            p01[i] = cmul(eV[0][(i >> 1) & 1], eV[1][i & 1]);
            p23[i] = cmul(eV[2][(i >> 1) & 1], eV[3][i & 1]);
        }
        u64* st = s ? sb : sa;
#pragma unroll
        for (int r = 0; r < NR; r++) {
            float2 a = cmul(cmul(p01[r >> 2], p23[r & 3]), cm);
            st[r] = pack2(a.x, a.y);
        }
    }

    // ---- layers (R13 schedule, paired; shared barriers) ----
    {
        sweep_D_to_A2(sa, sb, Usm +  0 * 48, t, xa0, xb0);
        diag_A2(sa, sb, t, &Phs2[0]);
        cnotx2<true>(sa, sb, t, xa1, xb1, units_sm[0]);
        diag_A2(sa, sb, t, &Phs1[12]);

        sweep_A_to_D2(sa, sb, Usm +  1 * 48, t, xa0, xb0);
        diag_D2(sa, sb, t, &Phs2[12]);
        cnotx2<false>(sa, sb, t, xa1, xb1, units_sm[1]);
        diag_D2(sa, sb, t, &Phs1[24]);

        sweep_D_to_A2(sa, sb, Usm +  2 * 48, t, xa0, xb0);
        diag_A2(sa, sb, t, &Phs2[24]);
        cnotx2<true>(sa, sb, t, xa1, xb1, units_sm[2]);
        diag_A2(sa, sb, t, &Phs1[36]);

        sweep_A_to_D2(sa, sb, Usm +  3 * 48, t, xa0, xb0);
        // D2_3 dropped: |amp|^2 is phase-invariant
        cnotx2<false>(sa, sb, t, xa1, xb1, units_sm[3]);
    }

    // ---- readout: sample a then sample b (independent smem scratch, shared bars) ----
    readout(sa, t, lane, wid, redA, &out[b0 * NQ]);
    readout(sb, t, lane, wid, redB, &out[(b0 + 1) * NQ]);
}

extern "C" void kernel_launch(void* const* d_in, const int* in_sizes, int n_in,
                              void* d_out, int out_size)
{
    const float* x   = (const float*)d_in[0];   // (B, 12)
    const float* w   = (const float*)d_in[1];   // (4, 12, 3)
    const float* ent = (const float*)d_in[2];   // (4, 12)
    float* out = (float*)d_out;                 // (B, 12)

    const size_t shmem = 4 * XSZ * sizeof(u64);  // 139264 B dynamic
    cudaFuncSetAttribute((const void*)qsim_kernel,
                         cudaFuncAttributeMaxDynamicSharedMemorySize, (int)shmem);

    int B = in_sizes[0] / NQ;
    qsim_kernel<<<B / 2, NT, shmem>>>(x, w, ent, out);
}